// round 8
// baseline (speedup 1.0000x reference)
#include <cuda_runtime.h>
#include <cuda_bf16.h>
#include <cstdint>

// MaskSupervisionLoss on GB300 (sm_103a) — cp.async pipeline + intra-block
// accumulator split (warps 0-3 / 4-7 share the smem tile; no traffic dup).
// Inputs: pred_attn f32 (32,8,256,256), gt_masks f32 (32,8,256,256), num_objects i32 (32)
// Output: scalar f32 loss.

#define NB     32
#define NSLOT  8
#define HW     65536
#define NCH    64
#define CPOS   1024                // positions per chunk
#define TILE   256                 // positions per tile
#define NTILE  (CPOS / TILE)       // 4
#define STAGES 3
#define TPB    256
#define NV     66
#define EPSF   1e-6f
#define NSTRM  16                  // 8 pred + 8 gt streams

// canonical layout (per batch):
//  0 bg_inter, 1 bg_psum, 2 bg_gsum, 3..9 psum fg0-6, 10..16 gsum fg0-6,
//  17..65 inter[p][g] = 17 + 7p + g

__device__ float g_scratch[NB * NCH * NV];
__device__ float g_batch[NB * 3];
__device__ int   g_cnt[NB];        // zero-init; self-resetting
__device__ int   g_cnt_all;        // zero-init; self-resetting

__device__ __forceinline__ void cp16(unsigned int dst_smem, const float* src) {
    asm volatile("cp.async.cg.shared.global [%0], [%1], 16;\n"
                 :: "r"(dst_smem), "l"(src));
}
__device__ __forceinline__ void cp_commit() {
    asm volatile("cp.async.commit_group;\n");
}
template <int N>
__device__ __forceinline__ void cp_wait() {
    asm volatile("cp.async.wait_group %0;\n" :: "n"(N));
}

// ---------------------------------------------------------------------------
__global__ __launch_bounds__(TPB, 3)
void k_fused(const float* __restrict__ pred, const float* __restrict__ gt,
             const int* __restrict__ nobj, float* __restrict__ out) {
    const int chunk = blockIdx.x;
    const int b     = blockIdx.y;
    const int tid   = threadIdx.x;
    const int wid   = tid >> 5;
    const int lane  = tid & 31;
    const bool grpB = (tid >= 128);
    const int  gtid = tid & 127;     // thread index within group

    __shared__ float buf[STAGES][NSTRM][TILE];   // 48 KB
    __shared__ float sw[8][34];
    __shared__ int   sflag;

    const float* __restrict__ bp = pred + (size_t)b * NSLOT * HW + chunk * CPOS;
    const float* __restrict__ bg = gt   + (size_t)b * NSLOT * HW + chunk * CPOS;

    const unsigned int smem_base =
        (unsigned int)__cvta_generic_to_shared(&buf[0][0][0]);

    // issue one tile's loads (1024 x 16B over 256 threads = 4 per thread)
    auto load_tile = [&](int t) {
        const int stage = t % STAGES;
        const int goff  = t * TILE;
#pragma unroll
        for (int k = 0; k < 4; k++) {
            const int o = k * TPB + tid;
            const int s = o >> 6;
            const int w = o & 63;
            const float* src = ((s < 8) ? (bp + s * HW) : (bg + (s - 8) * HW)) + goff + w * 4;
            cp16(smem_base + (unsigned int)(((stage * NSTRM + s) * TILE + w * 4) * 4), src);
        }
        cp_commit();
    };

    float acc[34];
#pragma unroll
    for (int v = 0; v < 34; v++) acc[v] = 0.f;

    // prologue: tiles 0 and 1
    load_tile(0);
    load_tile(1);

#pragma unroll
    for (int t = 0; t < NTILE; t++) {
        if (t < NTILE - 1) cp_wait<1>();   // tile t arrived (t+1 may be in flight)
        else               cp_wait<0>();
        __syncthreads();                   // tile t visible to all warps;
                                           // stage (t+2)%3 free for reuse
        if (t + 2 < NTILE) load_tile(t + 2);

        const int st = t % STAGES;
        if (!grpB) {
            // group A: pred slots 0-3, bg stats, gt sums, inter rows 0-2
            float2 p[4], g[8];
#pragma unroll
            for (int s = 0; s < 4; s++) p[s] = ((const float2*)&buf[st][s][0])[gtid];
#pragma unroll
            for (int s = 0; s < 8; s++) g[s] = ((const float2*)&buf[st][8 + s][0])[gtid];
            // .x
            acc[0] = fmaf(p[0].x, g[0].x, acc[0]);
            acc[1] += p[0].x;
            acc[2] += g[0].x;
#pragma unroll
            for (int r = 0; r < 3; r++) acc[3 + r] += p[r + 1].x;
#pragma unroll
            for (int c = 0; c < 7; c++) acc[6 + c] += g[c + 1].x;
#pragma unroll
            for (int r = 0; r < 3; r++)
#pragma unroll
                for (int c = 0; c < 7; c++)
                    acc[13 + r * 7 + c] = fmaf(p[r + 1].x, g[c + 1].x, acc[13 + r * 7 + c]);
            // .y
            acc[0] = fmaf(p[0].y, g[0].y, acc[0]);
            acc[1] += p[0].y;
            acc[2] += g[0].y;
#pragma unroll
            for (int r = 0; r < 3; r++) acc[3 + r] += p[r + 1].y;
#pragma unroll
            for (int c = 0; c < 7; c++) acc[6 + c] += g[c + 1].y;
#pragma unroll
            for (int r = 0; r < 3; r++)
#pragma unroll
                for (int c = 0; c < 7; c++)
                    acc[13 + r * 7 + c] = fmaf(p[r + 1].y, g[c + 1].y, acc[13 + r * 7 + c]);
        } else {
            // group B: pred slots 4-7, inter rows 3-6
            float2 p[4], g[7];
#pragma unroll
            for (int s = 0; s < 4; s++) p[s] = ((const float2*)&buf[st][4 + s][0])[gtid];
#pragma unroll
            for (int s = 0; s < 7; s++) g[s] = ((const float2*)&buf[st][9 + s][0])[gtid];
            // .x
#pragma unroll
            for (int r = 0; r < 4; r++) acc[r] += p[r].x;
#pragma unroll
            for (int r = 0; r < 4; r++)
#pragma unroll
                for (int c = 0; c < 7; c++)
                    acc[4 + r * 7 + c] = fmaf(p[r].x, g[c].x, acc[4 + r * 7 + c]);
            // .y
#pragma unroll
            for (int r = 0; r < 4; r++) acc[r] += p[r].y;
#pragma unroll
            for (int r = 0; r < 4; r++)
#pragma unroll
                for (int c = 0; c < 7; c++)
                    acc[4 + r * 7 + c] = fmaf(p[r].y, g[c].y, acc[4 + r * 7 + c]);
        }
    }

    // ---- block reduction: warp tree, then combine each group's 4 warps
    const int nval = grpB ? 32 : 34;
#pragma unroll
    for (int v = 0; v < 34; v++) {
        if (v < nval) {
            float x = acc[v];
#pragma unroll
            for (int o = 16; o > 0; o >>= 1) x += __shfl_down_sync(0xffffffffu, x, o);
            if (lane == 0) sw[wid][v] = x;
        }
    }
    __syncthreads();

    // publish canonical 66 values
    if (tid < 34) {
        const float s = sw[0][tid] + sw[1][tid] + sw[2][tid] + sw[3][tid];
        // A map: 0..2 -> 0..2 ; 3..5 -> 3..5 ; 6..12 -> 10..16 ; 13..33 -> 17..37
        const int v = (tid < 6) ? tid : tid + 4;
        g_scratch[(b * NCH + chunk) * NV + v] = s;
        __threadfence();
    } else if (tid < 66) {
        const int t = tid - 34;
        const float s = sw[4][t] + sw[5][t] + sw[6][t] + sw[7][t];
        // B map: 0..3 -> 6..9 ; 4..31 -> 38..65
        const int v = (t < 4) ? 6 + t : t + 34;
        g_scratch[(b * NCH + chunk) * NV + v] = s;
        __threadfence();
    }
    __syncthreads();

    if (tid == 0) sflag = (atomicAdd(&g_cnt[b], 1) == NCH - 1);
    __syncthreads();
    if (!sflag) return;

    // ================= batch finisher (last block of this batch) =============
    __shared__ float part[132];
    __shared__ float sm66[NV];
    __shared__ float dice[49];
    __shared__ float dpt[128];

    __threadfence();
    if (tid < 132) {
        const int v = tid >> 1, h = tid & 1;
        float s = 0.f;
#pragma unroll
        for (int c = 0; c < NCH / 2; c++)
            s += __ldcg(&g_scratch[(b * NCH + h * (NCH / 2) + c) * NV + v]);
        part[tid] = s;
    }
    __syncthreads();
    if (tid < NV) sm66[tid] = part[2 * tid] + part[2 * tid + 1];
    __syncthreads();
    if (tid < 49) {
        const int p = tid / 7, g = tid % 7;
        dice[tid] = (2.f * sm66[17 + tid] + EPSF) / (sm66[3 + p] + sm66[10 + g] + EPSF);
    }
    __syncthreads();

    if (wid == 0) {
        int n = nobj[b];
        n = (n > 7) ? 7 : (n < 0 ? 0 : n);
#pragma unroll
        for (int k = 0; k < 4; k++) dpt[k * 32 + lane] = -1e30f;
        __syncwarp();
        if (lane == 0) dpt[0] = 0.f;
        __syncwarp();
        // layered bitmask DP: optimal assignment value == Hungarian optimum
#pragma unroll
        for (int L = 1; L <= 7; L++) {
            const int g = L - 1;
            if (g < n) {
#pragma unroll
                for (int k = 0; k < 4; k++) {
                    const int m = k * 32 + lane;
                    if (__popc(m) == L) {
                        float best = -1e30f;
#pragma unroll
                        for (int p = 0; p < 7; p++)
                            if (m & (1 << p))
                                best = fmaxf(best, dpt[m ^ (1 << p)] + dice[p * 7 + g]);
                        dpt[m] = best;
                    }
                }
            }
            __syncwarp();
        }
        float best = -1e30f;
        if (n > 0) {
#pragma unroll
            for (int k = 0; k < 4; k++) {
                const int m = k * 32 + lane;
                if (__popc(m) == n) best = fmaxf(best, dpt[m]);
            }
        }
#pragma unroll
        for (int o = 16; o > 0; o >>= 1)
            best = fmaxf(best, __shfl_xor_sync(0xffffffffu, best, o));
        if (lane == 0) {
            g_batch[b * 3 + 0] = (2.f * sm66[0] + EPSF) / (sm66[1] + sm66[2] + EPSF);
            g_batch[b * 3 + 1] = (float)n;
            g_batch[b * 3 + 2] = (n > 0) ? best : 0.f;
        }
    }
    __syncthreads();

    if (tid == 0) {
        g_cnt[b] = 0;                       // reset for next graph replay
        __threadfence();
        sflag = (atomicAdd(&g_cnt_all, 1) == NB - 1);
    }
    __syncthreads();
    if (!sflag) return;

    // ================= global finisher =================
    if (wid == 0) {
        __threadfence();
        const float bgd = __ldcg(&g_batch[lane * 3 + 0]);
        const float nn  = __ldcg(&g_batch[lane * 3 + 1]);
        const float sv  = __ldcg(&g_batch[lane * 3 + 2]);
        float bg  = 1.f - bgd;
        float tot = nn;
        float ss  = (nn > 0.f) ? sv : 0.f;
#pragma unroll
        for (int o = 16; o > 0; o >>= 1) {
            bg  += __shfl_xor_sync(0xffffffffu, bg,  o);
            tot += __shfl_xor_sync(0xffffffffu, tot, o);
            ss  += __shfl_xor_sync(0xffffffffu, ss,  o);
        }
        if (lane == 0) {
            const float fg = (tot > 0.f) ? (tot - ss) / tot : 0.f;
            out[0] = bg * (1.f / (float)NB) + fg;
            g_cnt_all = 0;                  // reset for next graph replay
        }
    }
}

// ---------------------------------------------------------------------------
extern "C" void kernel_launch(void* const* d_in, const int* in_sizes, int n_in,
                              void* d_out, int out_size) {
    const float* pred = (const float*)d_in[0];
    const float* gt   = (const float*)d_in[1];
    const int*   nobj = (const int*)d_in[2];
    float*       out  = (float*)d_out;

    dim3 grid(NCH, NB);
    k_fused<<<grid, TPB>>>(pred, gt, nobj, out);
}

// round 9
// speedup vs baseline: 1.1794x; 1.1794x over previous
#include <cuda_runtime.h>
#include <cuda_bf16.h>
#include <cstdint>

// MaskSupervisionLoss on GB300 (sm_103a) — persistent single-wave kernel with
// per-warp barrier-free cp.async pipelines.
// Inputs: pred_attn f32 (32,8,256,256), gt_masks f32 (32,8,256,256), num_objects i32 (32)
// Output: scalar f32 loss.

#define NB      32
#define NSLOT   8
#define HW      65536
#define CTAB    18                 // CTAs per batch (18*32 = 576 <= 592 slots)
#define TILE    128                // positions per tile
#define TPBT    512                // tiles per batch (HW/TILE)
#define STAGES  5
#define TPB     128
#define NV      66
#define EPSF    1e-6f

// canonical layout (per batch):
//  0 bg_inter, 1 bg_psum, 2 bg_gsum, 3..9 psum fg0-6, 10..16 gsum fg0-6,
//  17..65 inter[p][g] = 17 + 7p + g

__device__ float g_scratch[NB * CTAB * NV];
__device__ float g_batch[NB * 3];
__device__ int   g_cnt[NB];        // zero-init; self-resetting
__device__ int   g_cnt_all;        // zero-init; self-resetting

__device__ __forceinline__ void cp16(unsigned int dst_smem, const float* src) {
    asm volatile("cp.async.cg.shared.global [%0], [%1], 16;\n"
                 :: "r"(dst_smem), "l"(src));
}
__device__ __forceinline__ void cp_commit() {
    asm volatile("cp.async.commit_group;\n");
}
template <int N>
__device__ __forceinline__ void cp_wait() {
    asm volatile("cp.async.wait_group %0;\n" :: "n"(N));
}

// ---------------------------------------------------------------------------
__global__ __launch_bounds__(TPB, 4)
void k_fused(const float* __restrict__ pred, const float* __restrict__ gt,
             const int* __restrict__ nobj, float* __restrict__ out) {
    const int idx  = blockIdx.x;       // 0..17 within batch
    const int b    = blockIdx.y;
    const int tid  = threadIdx.x;
    const int wid  = tid >> 5;
    const int lane = tid & 31;

    // tile range for this CTA: 8 CTAs get 29 tiles, 10 get 28 (8*29+10*28=512)
    const int t0  = (idx < 8) ? idx * 29 : 232 + (idx - 8) * 28;
    const int cnt = (idx < 8) ? 29 : 28;

    // stage = 16 streams x 128 floats = 8KB ; 5 stages = 40KB
    __shared__ float buf[STAGES][16][TILE];
    __shared__ float sw[4][NV];
    __shared__ int   sflag;

    const float* __restrict__ bp = pred + (size_t)b * NSLOT * HW;
    const float* __restrict__ bg = gt   + (size_t)b * NSLOT * HW;

    // per-thread cp.async mapping: warp w loads the 16 x 128B segments that its
    // own lanes consume (positions 32w .. 32w+31). 4 cp16 (16B) per lane/tile.
    //   j-th op: idx = j*32 + lane ; stream s = idx>>3 ; 16B unit u = idx&7
    const unsigned int smem0 = (unsigned int)__cvta_generic_to_shared(&buf[0][0][0]);
    const float* srcp[4];
    unsigned int dstb[4];
#pragma unroll
    for (int j = 0; j < 4; j++) {
        const int o = j * 32 + lane;
        const int s = o >> 3;
        const int u = o & 7;
        const float* sb = (s < 8) ? (bp + s * HW) : (bg + (s - 8) * HW);
        srcp[j] = sb + (size_t)t0 * TILE + wid * 32 + u * 4;
        dstb[j] = smem0 + (unsigned int)((s * TILE + wid * 32 + u * 4) * 4);
    }

    float acc[NV];
#pragma unroll
    for (int v = 0; v < NV; v++) acc[v] = 0.f;

    // ---- prologue: issue tiles 0..3 (4 groups per warp)
#pragma unroll
    for (int T = 0; T < 4; T++) {
        const unsigned int so = (unsigned int)((T % STAGES) * 16 * TILE * 4);
#pragma unroll
        for (int j = 0; j < 4; j++)
            cp16(dstb[j] + so, srcp[j] + (size_t)T * TILE);
        cp_commit();
    }

    // ---- main loop: one group committed per iter (empty in tail) keeps
    //      wait<3> => tile t complete. No __syncthreads: warps independent.
    for (int t = 0; t < cnt; t++) {
        if (t + 4 < cnt) {
            const int T = t + 4;
            const unsigned int so = (unsigned int)((T % STAGES) * 16 * TILE * 4);
#pragma unroll
            for (int j = 0; j < 4; j++)
                cp16(dstb[j] + so, srcp[j] + (size_t)T * TILE);
        }
        cp_commit();
        cp_wait<3>();

        const float* tb = &buf[t % STAGES][0][0] + tid;   // stream s at tb[s*TILE]
        float v[16];
#pragma unroll
        for (int s = 0; s < 16; s++) v[s] = tb[s * TILE];

        // v[0..7] = pred slots, v[8..15] = gt slots
        acc[0] = fmaf(v[0], v[8], acc[0]);
        acc[1] += v[0];
        acc[2] += v[8];
#pragma unroll
        for (int r = 0; r < 7; r++) acc[3 + r]  += v[1 + r];
#pragma unroll
        for (int c = 0; c < 7; c++) acc[10 + c] += v[9 + c];
#pragma unroll
        for (int r = 0; r < 7; r++)
#pragma unroll
            for (int c = 0; c < 7; c++)
                acc[17 + r * 7 + c] = fmaf(v[1 + r], v[9 + c], acc[17 + r * 7 + c]);
    }
    cp_wait<0>();

    // ---- block reduction: warp tree + 4-warp combine, publish canonical 66
#pragma unroll
    for (int v = 0; v < NV; v++) {
        float x = acc[v];
#pragma unroll
        for (int o = 16; o > 0; o >>= 1) x += __shfl_down_sync(0xffffffffu, x, o);
        if (lane == 0) sw[wid][v] = x;
    }
    __syncthreads();

    if (tid < NV) {
        g_scratch[(b * CTAB + idx) * NV + tid] =
            sw[0][tid] + sw[1][tid] + sw[2][tid] + sw[3][tid];
        __threadfence();
    }
    __syncthreads();

    if (tid == 0) sflag = (atomicAdd(&g_cnt[b], 1) == CTAB - 1);
    __syncthreads();
    if (!sflag) return;

    // ================= batch finisher (last CTA of this batch) ===============
    __shared__ float part[132];
    __shared__ float sm66[NV];
    __shared__ float dice[49];
    __shared__ float dpt[128];

    __threadfence();
    for (int e = tid; e < 132; e += TPB) {
        const int v = e >> 1, h = e & 1;
        float s = 0.f;
#pragma unroll
        for (int c = 0; c < CTAB / 2; c++)
            s += __ldcg(&g_scratch[(b * CTAB + h * (CTAB / 2) + c) * NV + v]);
        part[e] = s;
    }
    __syncthreads();
    if (tid < NV) sm66[tid] = part[2 * tid] + part[2 * tid + 1];
    __syncthreads();
    if (tid < 49) {
        const int p = tid / 7, g = tid % 7;
        dice[tid] = (2.f * sm66[17 + tid] + EPSF) / (sm66[3 + p] + sm66[10 + g] + EPSF);
    }
    __syncthreads();

    if (wid == 0) {
        int n = nobj[b];
        n = (n > 7) ? 7 : (n < 0 ? 0 : n);
#pragma unroll
        for (int k = 0; k < 4; k++) dpt[k * 32 + lane] = -1e30f;
        __syncwarp();
        if (lane == 0) dpt[0] = 0.f;
        __syncwarp();
        // layered bitmask DP: optimal assignment value == Hungarian optimum
#pragma unroll
        for (int L = 1; L <= 7; L++) {
            const int g = L - 1;
            if (g < n) {
#pragma unroll
                for (int k = 0; k < 4; k++) {
                    const int m = k * 32 + lane;
                    if (__popc(m) == L) {
                        float best = -1e30f;
#pragma unroll
                        for (int p = 0; p < 7; p++)
                            if (m & (1 << p))
                                best = fmaxf(best, dpt[m ^ (1 << p)] + dice[p * 7 + g]);
                        dpt[m] = best;
                    }
                }
            }
            __syncwarp();
        }
        float best = -1e30f;
        if (n > 0) {
#pragma unroll
            for (int k = 0; k < 4; k++) {
                const int m = k * 32 + lane;
                if (__popc(m) == n) best = fmaxf(best, dpt[m]);
            }
        }
#pragma unroll
        for (int o = 16; o > 0; o >>= 1)
            best = fmaxf(best, __shfl_xor_sync(0xffffffffu, best, o));
        if (lane == 0) {
            g_batch[b * 3 + 0] = (2.f * sm66[0] + EPSF) / (sm66[1] + sm66[2] + EPSF);
            g_batch[b * 3 + 1] = (float)n;
            g_batch[b * 3 + 2] = (n > 0) ? best : 0.f;
        }
    }
    __syncthreads();

    if (tid == 0) {
        g_cnt[b] = 0;                       // reset for next graph replay
        __threadfence();
        sflag = (atomicAdd(&g_cnt_all, 1) == NB - 1);
    }
    __syncthreads();
    if (!sflag) return;

    // ================= global finisher =================
    if (wid == 0) {
        __threadfence();
        const float bgd = __ldcg(&g_batch[lane * 3 + 0]);
        const float nn  = __ldcg(&g_batch[lane * 3 + 1]);
        const float sv  = __ldcg(&g_batch[lane * 3 + 2]);
        float bg  = 1.f - bgd;
        float tot = nn;
        float ss  = (nn > 0.f) ? sv : 0.f;
#pragma unroll
        for (int o = 16; o > 0; o >>= 1) {
            bg  += __shfl_xor_sync(0xffffffffu, bg,  o);
            tot += __shfl_xor_sync(0xffffffffu, tot, o);
            ss  += __shfl_xor_sync(0xffffffffu, ss,  o);
        }
        if (lane == 0) {
            const float fg = (tot > 0.f) ? (tot - ss) / tot : 0.f;
            out[0] = bg * (1.f / (float)NB) + fg;
            g_cnt_all = 0;                  // reset for next graph replay
        }
    }
}

// ---------------------------------------------------------------------------
extern "C" void kernel_launch(void* const* d_in, const int* in_sizes, int n_in,
                              void* d_out, int out_size) {
    const float* pred = (const float*)d_in[0];
    const float* gt   = (const float*)d_in[1];
    const int*   nobj = (const int*)d_in[2];
    float*       out  = (float*)d_out;

    dim3 grid(CTAB, NB);
    k_fused<<<grid, TPB>>>(pred, gt, nobj, out);
}